// round 6
// baseline (speedup 1.0000x reference)
#include <cuda_runtime.h>
#include <cuda_fp16.h>
#include <stdint.h>

#define D_MODEL 2048
#define H_FF    1408
#define NE      8
#define NTOK    8192
#define SLOTS   16384
#define CAP     2048
#define BK      32                 // halfs per k-tile (64B fp16 rows)

#define NT1     (D_MODEL / BK)     // 64
#define NT3     (H_FF / BK)        // 44

// smem stage layout (bytes): rows padded to 80B (20 words; conflict-free)
#define G1_BG   10240
#define G1_BU   20480
#define G3_B    10240
#define STG     30720
#define SMEM_SZ (3 * STG)          // 92160

// ---------------- scratch ----------------
__device__ int    g_cnt[NE];
__device__ int    g_tok[SLOTS];
__device__ float  g_scr[SLOTS];
__device__ __half g_xh [(size_t)NTOK * D_MODEL];   // fp16 row-major [tok][d]
__device__ __half g_Hh [(size_t)SLOTS * H_FF];     // [slot][h] fp16

// ---------------- helpers ----------------
__device__ __forceinline__ uint32_t smem_u32(const void* p) {
    uint32_t a;
    asm("{ .reg .u64 t; cvta.to.shared.u64 t, %1; cvt.u32.u64 %0, t; }" : "=r"(a) : "l"(p));
    return a;
}
__device__ __forceinline__ void cp16(uint32_t dst, const void* src) {
    asm volatile("cp.async.cg.shared.global [%0], [%1], 16;" :: "r"(dst), "l"(src));
}
__device__ __forceinline__ void cp_commit() { asm volatile("cp.async.commit_group;"); }
__device__ __forceinline__ void cp_wait1() { asm volatile("cp.async.wait_group 1;"); }
__device__ __forceinline__ void cp_wait0() { asm volatile("cp.async.wait_group 0;"); }

__device__ __forceinline__ void mma16(float* d, const uint32_t* a, const uint32_t* b) {
    asm volatile(
        "mma.sync.aligned.m16n8k16.row.col.f32.f16.f16.f32 "
        "{%0,%1,%2,%3}, {%4,%5,%6,%7}, {%8,%9}, {%0,%1,%2,%3};\n"
        : "+f"(d[0]), "+f"(d[1]), "+f"(d[2]), "+f"(d[3])
        : "r"(a[0]), "r"(a[1]), "r"(a[2]), "r"(a[3]), "r"(b[0]), "r"(b[1]));
}
__device__ __forceinline__ void sts128(uint32_t a, uint32_t r0, uint32_t r1,
                                       uint32_t r2, uint32_t r3) {
    asm volatile("st.shared.v4.b32 [%0], {%1,%2,%3,%4};"
        :: "r"(a), "r"(r0), "r"(r1), "r"(r2), "r"(r3) : "memory");
}
__device__ __forceinline__ uint32_t h2u(float a, float b) {
    __half2 h = __floats2half2_rn(a, b);
    return *(uint32_t*)&h;
}

// ---------------- pre-pass kernels ----------------
// zero y + convert x->fp16 + reset routing counters, all in one launch
__global__ void prep_kernel(const float4* __restrict__ x, float4* __restrict__ y, int n4) {
    int i = blockIdx.x * blockDim.x + threadIdx.x;
    if (i < n4) {
        y[i] = make_float4(0.f, 0.f, 0.f, 0.f);
        float4 v = x[i];
        uint2 o;
        o.x = h2u(v.x, v.y);
        o.y = h2u(v.z, v.w);
        ((uint2*)g_xh)[i] = o;
    }
    if (blockIdx.x == 0 && threadIdx.x < NE) g_cnt[threadIdx.x] = 0;
}

__global__ void route_kernel(const int* __restrict__ idx, const float* __restrict__ scr) {
    int s = blockIdx.x * blockDim.x + threadIdx.x;
    if (s < SLOTS) {
        int e = idx[s];
        int p = atomicAdd(&g_cnt[e], 1);
        g_tok[e * CAP + p] = s >> 1;     // TOP_K = 2
        g_scr[e * CAP + p] = scr[s];
    }
}

// ---------------------------------------------------------------------------
// GEMM1+2 fused (fp16 mma, fp32 weights converted in-loop).
// CTA: 128 slots x 128 h for BOTH gate and up. 8 warps 2x4, warp 64x32 each.
// A: cp.async fp16 (3-stage). B: per-thread row, 32 coalesced LDG.32 fp32,
// cvt -> 4 STS.128, register-pipelined one k-tile ahead.
// ---------------------------------------------------------------------------
__global__ void __launch_bounds__(256, 1) g1_kernel(
    const float* __restrict__ Wg, const float* __restrict__ Wu)
{
    extern __shared__ uint32_t sm[];
    const int tid = threadIdx.x, lane = tid & 31, w = tid >> 5;
    const int wm = w >> 2, wn = w & 3;
    const int ql = lane >> 2, qc = lane & 3;
    const int e = blockIdx.z, bm = blockIdx.x, bn = blockIdx.y;
    const uint32_t sbase = smem_u32(sm);

    // A loader: thread covers rows r4, r4+64 (16B chunk ck) of gathered x
    const int r4 = tid >> 2, ck = tid & 3;
    const __half* ap0 = g_xh + (size_t)g_tok[e * CAP + bm * 128 + r4] * D_MODEL + ck * 8;
    const __half* ap1 = g_xh + (size_t)g_tok[e * CAP + bm * 128 + r4 + 64] * D_MODEL + ck * 8;
    const uint32_t ad0 = sbase + r4 * 80 + ck * 16, ad1 = ad0 + 64 * 80;

    // B loader: thread -> one n-row. t<128: gate row t; t>=128: up row t-128.
    const int brow = tid & 127;
    const float* bp = (tid < 128 ? Wg : Wu)
                    + (size_t)e * D_MODEL * H_FF + (size_t)bn * 128 + brow;
    const uint32_t bds = (tid < 128 ? G1_BG : G1_BU) + brow * 80;

    float accg[4][4][4], accu[4][4][4];
    #pragma unroll
    for (int mi = 0; mi < 4; mi++)
        #pragma unroll
        for (int ni = 0; ni < 4; ni++)
            #pragma unroll
            for (int q = 0; q < 4; q++) { accg[mi][ni][q] = 0.f; accu[mi][ni][q] = 0.f; }

    float bf[32];
    // prologue: B(0) into regs; A stages 0,1 via cp.async
    #pragma unroll
    for (int j = 0; j < 32; j++) bf[j] = bp[(size_t)j * H_FF];
    #pragma unroll
    for (int s = 0; s < 2; s++) {
        const uint32_t so = s * STG;
        cp16(ad0 + so, ap0 + s * BK); cp16(ad1 + so, ap1 + s * BK);
        cp_commit();
    }

    for (int kt = 0; kt < NT1; kt++) {
        const int s = kt % 3;
        // STS B(kt) from regs (loaded during kt-1)
        {
            const uint32_t d = sbase + s * STG + bds;
            #pragma unroll
            for (int c = 0; c < 4; c++)
                sts128(d + c * 16,
                       h2u(bf[c * 8 + 0], bf[c * 8 + 1]), h2u(bf[c * 8 + 2], bf[c * 8 + 3]),
                       h2u(bf[c * 8 + 4], bf[c * 8 + 5]), h2u(bf[c * 8 + 6], bf[c * 8 + 7]));
        }
        // issue LDG B(kt+1)
        if (kt + 1 < NT1) {
            const float* bpk = bp + (size_t)(kt + 1) * BK * H_FF;
            #pragma unroll
            for (int j = 0; j < 32; j++) bf[j] = bpk[(size_t)j * H_FF];
        }
        if (kt >= NT1 - 2) cp_wait0(); else cp_wait1();
        __syncthreads();
        // prefetch A(kt+2)
        if (kt + 2 < NT1) {
            const uint32_t so = ((kt + 2) % 3) * STG;
            cp16(ad0 + so, ap0 + (kt + 2) * BK); cp16(ad1 + so, ap1 + (kt + 2) * BK);
            cp_commit();
        }

        const uint32_t* As = sm + s * (STG / 4);
        const uint32_t* Bg = As + G1_BG / 4;
        const uint32_t* Bu = As + G1_BU / 4;
        #pragma unroll
        for (int kk = 0; kk < 2; kk++) {
            const int kb = kk * 8 + qc;
            uint32_t af[4][4];
            #pragma unroll
            for (int mi = 0; mi < 4; mi++) {
                const int r = wm * 64 + mi * 16 + ql;
                af[mi][0] = As[r * 20 + kb];
                af[mi][1] = As[(r + 8) * 20 + kb];
                af[mi][2] = As[r * 20 + kb + 4];
                af[mi][3] = As[(r + 8) * 20 + kb + 4];
            }
            #pragma unroll
            for (int ni = 0; ni < 4; ni++) {
                const int nn = wn * 32 + ni * 8 + ql;
                uint32_t bg[2] = { Bg[nn * 20 + kb], Bg[nn * 20 + kb + 4] };
                uint32_t bu[2] = { Bu[nn * 20 + kb], Bu[nn * 20 + kb + 4] };
                #pragma unroll
                for (int mi = 0; mi < 4; mi++) {
                    mma16(accg[mi][ni], af[mi], bg);
                    mma16(accu[mi][ni], af[mi], bu);
                }
            }
        }
        __syncthreads();
    }

    // epilogue: h = silu(g)*u -> fp16 H
    const size_t rowBase = (size_t)e * CAP + (size_t)bm * 128;
    const int colBase = bn * 128 + wn * 32;
    #pragma unroll
    for (int mi = 0; mi < 4; mi++)
        #pragma unroll
        for (int ni = 0; ni < 4; ni++)
            #pragma unroll
            for (int q2 = 0; q2 < 2; q2++) {
                const int r = wm * 64 + mi * 16 + ql + q2 * 8;
                float g0 = accg[mi][ni][q2 * 2],     u0 = accu[mi][ni][q2 * 2];
                float g1 = accg[mi][ni][q2 * 2 + 1], u1 = accu[mi][ni][q2 * 2 + 1];
                float h0 = (g0 / (1.f + __expf(-g0))) * u0;
                float h1 = (g1 / (1.f + __expf(-g1))) * u1;
                *(__half2*)(g_Hh + (rowBase + r) * H_FF + colBase + ni * 8 + 2 * qc) =
                    __floats2half2_rn(h0, h1);
            }
}

// ---------------------------------------------------------------------------
// GEMM3 (fp16 mma, fp32 Wd converted in-loop): y[tok] += score * (H @ Wd).
// CTA: 128 slots x 256 d. Warp tile 64x64. K = H_FF.
// ---------------------------------------------------------------------------
__global__ void __launch_bounds__(256, 1) g3_kernel(
    const float* __restrict__ Wd, float* __restrict__ y)
{
    extern __shared__ uint32_t sm[];
    __shared__ int   sTok[128];
    __shared__ float sScr[128];
    const int tid = threadIdx.x, lane = tid & 31, w = tid >> 5;
    const int wm = w >> 2, wn = w & 3;
    const int ql = lane >> 2, qc = lane & 3;
    const int e = blockIdx.z, bm = blockIdx.x, bn = blockIdx.y;
    const uint32_t sbase = smem_u32(sm);

    if (tid < 128) {
        int slot = e * CAP + bm * 128 + tid;
        sTok[tid] = g_tok[slot];
        sScr[tid] = g_scr[slot];
    }

    const int r4 = tid >> 2, ck = tid & 3;
    const __half* ap0 = g_Hh + ((size_t)e * CAP + (size_t)bm * 128 + r4) * H_FF + ck * 8;
    const __half* ap1 = ap0 + (size_t)64 * H_FF;
    const uint32_t ad0 = sbase + r4 * 80 + ck * 16, ad1 = ad0 + 64 * 80;

    // B loader: thread -> one n-row (256 rows). Wd layout [e][k=H_FF][n=D_MODEL]
    const float* bp = Wd + (size_t)e * H_FF * D_MODEL + (size_t)bn * 256 + tid;
    const uint32_t bds = G3_B + tid * 80;

    float acc[4][8][4];
    #pragma unroll
    for (int mi = 0; mi < 4; mi++)
        #pragma unroll
        for (int ni = 0; ni < 8; ni++)
            #pragma unroll
            for (int q = 0; q < 4; q++) acc[mi][ni][q] = 0.f;

    float bf[32];
    #pragma unroll
    for (int j = 0; j < 32; j++) bf[j] = bp[(size_t)j * D_MODEL];
    #pragma unroll
    for (int s = 0; s < 2; s++) {
        const uint32_t so = s * STG;
        cp16(ad0 + so, ap0 + s * BK); cp16(ad1 + so, ap1 + s * BK);
        cp_commit();
    }

    for (int kt = 0; kt < NT3; kt++) {
        const int s = kt % 3;
        {
            const uint32_t d = sbase + s * STG + bds;
            #pragma unroll
            for (int c = 0; c < 4; c++)
                sts128(d + c * 16,
                       h2u(bf[c * 8 + 0], bf[c * 8 + 1]), h2u(bf[c * 8 + 2], bf[c * 8 + 3]),
                       h2u(bf[c * 8 + 4], bf[c * 8 + 5]), h2u(bf[c * 8 + 6], bf[c * 8 + 7]));
        }
        if (kt + 1 < NT3) {
            const float* bpk = bp + (size_t)(kt + 1) * BK * D_MODEL;
            #pragma unroll
            for (int j = 0; j < 32; j++) bf[j] = bpk[(size_t)j * D_MODEL];
        }
        if (kt >= NT3 - 2) cp_wait0(); else cp_wait1();
        __syncthreads();
        if (kt + 2 < NT3) {
            const uint32_t so = ((kt + 2) % 3) * STG;
            cp16(ad0 + so, ap0 + (kt + 2) * BK); cp16(ad1 + so, ap1 + (kt + 2) * BK);
            cp_commit();
        }

        const uint32_t* As = sm + s * (STG / 4);
        const uint32_t* Bs = As + G3_B / 4;
        #pragma unroll
        for (int kk = 0; kk < 2; kk++) {
            const int kb = kk * 8 + qc;
            uint32_t af[4][4];
            #pragma unroll
            for (int mi = 0; mi < 4; mi++) {
                const int r = wm * 64 + mi * 16 + ql;
                af[mi][0] = As[r * 20 + kb];
                af[mi][1] = As[(r + 8) * 20 + kb];
                af[mi][2] = As[r * 20 + kb + 4];
                af[mi][3] = As[(r + 8) * 20 + kb + 4];
            }
            #pragma unroll
            for (int ni = 0; ni < 8; ni++) {
                const int nn = wn * 64 + ni * 8 + ql;
                uint32_t bw[2] = { Bs[nn * 20 + kb], Bs[nn * 20 + kb + 4] };
                #pragma unroll
                for (int mi = 0; mi < 4; mi++)
                    mma16(acc[mi][ni], af[mi], bw);
            }
        }
        __syncthreads();
    }

    // epilogue: scale + atomic combine
    const int colBase = bn * 256 + wn * 64;
    #pragma unroll
    for (int mi = 0; mi < 4; mi++) {
        #pragma unroll
        for (int q2 = 0; q2 < 2; q2++) {
            const int r = wm * 64 + mi * 16 + ql + q2 * 8;
            const float sc = sScr[r];
            float* yrow = y + (size_t)sTok[r] * D_MODEL + colBase;
            #pragma unroll
            for (int ni = 0; ni < 8; ni++) {
                const int n0 = ni * 8 + 2 * qc;
                atomicAdd(yrow + n0,     acc[mi][ni][q2 * 2]     * sc);
                atomicAdd(yrow + n0 + 1, acc[mi][ni][q2 * 2 + 1] * sc);
            }
        }
    }
}

// ---------------------------------------------------------------------------
extern "C" void kernel_launch(void* const* d_in, const int* in_sizes, int n_in,
                              void* d_out, int out_size) {
    (void)in_sizes; (void)n_in; (void)out_size;
    const float* x   = (const float*)d_in[0];
    const int*   idx = (const int*)d_in[1];
    const float* scr = (const float*)d_in[2];
    const float* Wg  = (const float*)d_in[3];
    const float* Wu  = (const float*)d_in[4];
    const float* Wd  = (const float*)d_in[5];
    float* y = (float*)d_out;

    const int n4x = NTOK * D_MODEL / 4;
    prep_kernel<<<(n4x + 255) / 256, 256>>>((const float4*)x, (float4*)y, n4x);
    route_kernel<<<SLOTS / 256, 256>>>(idx, scr);

    cudaFuncSetAttribute(g1_kernel, cudaFuncAttributeMaxDynamicSharedMemorySize, SMEM_SZ);
    cudaFuncSetAttribute(g3_kernel, cudaFuncAttributeMaxDynamicSharedMemorySize, SMEM_SZ);

    dim3 grid1(CAP / 128, H_FF / 128, NE);    // (16, 11, 8)
    g1_kernel<<<grid1, 256, SMEM_SZ>>>(Wg, Wu);
    dim3 grid3(CAP / 128, D_MODEL / 256, NE); // (16, 8, 8)
    g3_kernel<<<grid3, 256, SMEM_SZ>>>(Wd, y);
}